// round 3
// baseline (speedup 1.0000x reference)
#include <cuda_runtime.h>

#define DM 1024
#define NH 16
#define DH 64
#define BB 2
#define SS 2048
#define MT (BB*SS)

// Scratch (device globals; no allocation allowed in kernel_launch)
__device__ float g_qh[MT*DM];   // [B,H,S,DH]
__device__ float g_kh[MT*DM];
__device__ float g_vh[MT*DM];
__device__ float g_at[MT*DM];   // merged-head attention output [B,S,DM]

// ---------------------------------------------------------------------------
__device__ __forceinline__ unsigned tf32r(float x) {
    unsigned u;
    asm("cvt.rna.tf32.f32 %0, %1;" : "=r"(u) : "f"(x));
    return u;
}

__device__ __forceinline__ void mma_tf32(float c[4], const unsigned a[4],
                                         const unsigned b[2]) {
    asm volatile(
        "mma.sync.aligned.m16n8k8.row.col.f32.tf32.tf32.f32 "
        "{%0,%1,%2,%3}, {%4,%5,%6,%7}, {%8,%9}, {%0,%1,%2,%3};"
        : "+f"(c[0]), "+f"(c[1]), "+f"(c[2]), "+f"(c[3])
        : "r"(a[0]), "r"(a[1]), "r"(a[2]), "r"(a[3]), "r"(b[0]), "r"(b[1]));
}

// ---------------------------------------------------------------------------
// TF32 GEMM: out[M,1024] = A[M,1024] @ W[1024,1024] + bias.
// Block 128x128, BK=32, 128 threads (4 warps), warp tile 64x64, 2 CTAs/SM.
// Fragment-layout smem; staging uses paired STS.64 (rg pairs adjacent).
// ---------------------------------------------------------------------------
__global__ __launch_bounds__(128, 2) void gemm_tf32(
    const float* __restrict__ A, const float* __restrict__ W,
    const float* __restrict__ bias, float* __restrict__ out, int split)
{
    __shared__ __align__(16) unsigned As[4 * 8 * 128];   // [kt][mt8][lane*4+rg]
    __shared__ __align__(16) unsigned Bs[4 * 16 * 64];   // [kt][nt16][lane*2+rg]

    const int tid  = threadIdx.x;
    const int lane = tid & 31, wid = tid >> 5;
    const int g = lane >> 2, t = lane & 3;
    const int bm = blockIdx.y * 128, bn = blockIdx.x * 128;
    const int mt0 = (wid >> 1) * 4;   // 4 m16 tiles per warp
    const int nt0 = (wid & 1) * 8;    // 8 n8 tiles per warp

    float acc[4][8][4];
    #pragma unroll
    for (int i = 0; i < 4; i++)
        #pragma unroll
        for (int j = 0; j < 8; j++)
            #pragma unroll
            for (int r = 0; r < 4; r++) acc[i][j][r] = 0.f;

    for (int k0 = 0; k0 < DM; k0 += 32) {
        // Stage A (128x32): pairs of rows (m, m+8) -> rg pairs {0,1} or {2,3}
        #pragma unroll
        for (int i = 0; i < 4; i++) {
            int idx = i * 128 + tid;
            int kq = (idx & 7) << 2;      // 0,4,...,28
            int row_id = idx >> 3;        // 0..63
            int mt = row_id >> 3, rl = row_id & 7;
            const float* p = A + (size_t)(bm + mt * 16 + rl) * DM + k0 + kq;
            float4 v0 = *(const float4*)p;
            float4 v1 = *(const float4*)(p + 8 * DM);
            float f0[4] = {v0.x, v0.y, v0.z, v0.w};
            float f1[4] = {v1.x, v1.y, v1.z, v1.w};
            int kt = kq >> 3;
            int rb = ((kq >> 2) & 1) << 1;
            unsigned* base = &As[((kt * 8 + mt) * 32 + (rl << 2)) * 4 + rb];
            #pragma unroll
            for (int j = 0; j < 4; j++) {
                uint2 pr = make_uint2(tf32r(f0[j]), tf32r(f1[j]));
                *(uint2*)(base + j * 4) = pr;
            }
        }
        // Stage B (32x128): pairs of rows (kk, kk+4) -> rg pair {0,1}
        #pragma unroll
        for (int i = 0; i < 4; i++) {
            int idx = i * 128 + tid;
            int nq = (idx & 31) << 2;     // 0..124
            int kid = idx >> 5;           // 0..15
            int kt = kid >> 2, kr = kid & 3;
            const float* p = W + (size_t)(k0 + kt * 8 + kr) * DM + bn + nq;
            float4 v0 = *(const float4*)p;
            float4 v1 = *(const float4*)(p + 4 * DM);
            float f0[4] = {v0.x, v0.y, v0.z, v0.w};
            float f1[4] = {v1.x, v1.y, v1.z, v1.w};
            #pragma unroll
            for (int j = 0; j < 4; j++) {
                int n = nq + j, nt = n >> 3;
                int ln = ((n & 7) << 2) | kr;
                uint2 pr = make_uint2(tf32r(f0[j]), tf32r(f1[j]));
                *(uint2*)&Bs[((kt * 16 + nt) * 32 + ln) * 2] = pr;
            }
        }
        __syncthreads();

        #pragma unroll
        for (int kt = 0; kt < 4; kt++) {
            unsigned a[4][4], b[8][2];
            #pragma unroll
            for (int im = 0; im < 4; im++)
                *(uint4*)a[im] = *(const uint4*)&As[((kt * 8 + mt0 + im) * 32 + lane) * 4];
            #pragma unroll
            for (int jn = 0; jn < 8; jn++)
                *(uint2*)b[jn] = *(const uint2*)&Bs[((kt * 16 + nt0 + jn) * 32 + lane) * 2];
            #pragma unroll
            for (int im = 0; im < 4; im++)
                #pragma unroll
                for (int jn = 0; jn < 8; jn++)
                    mma_tf32(acc[im][jn], a[im], b[jn]);
        }
        __syncthreads();
    }

    // Epilogue
    #pragma unroll
    for (int im = 0; im < 4; im++) {
        int r0 = bm + (wid >> 1) * 64 + im * 16 + g;
        int r1 = r0 + 8;
        #pragma unroll
        for (int jn = 0; jn < 8; jn++) {
            int col = bn + (wid & 1) * 64 + jn * 8 + t * 2;
            float b0 = bias[col], b1 = bias[col + 1];
            float v00 = acc[im][jn][0] + b0, v01 = acc[im][jn][1] + b1;
            float v10 = acc[im][jn][2] + b0, v11 = acc[im][jn][3] + b1;
            if (split) {
                int h = col >> 6, d = col & 63;
                int b_0 = r0 >> 11, s_0 = r0 & (SS - 1);
                int b_1 = r1 >> 11, s_1 = r1 & (SS - 1);
                float* p0 = out + (((size_t)(b_0 * NH + h)) * SS + s_0) * DH + d;
                float* p1 = out + (((size_t)(b_1 * NH + h)) * SS + s_1) * DH + d;
                p0[0] = v00; p0[1] = v01;
                p1[0] = v10; p1[1] = v11;
            } else {
                float* p0 = out + (size_t)r0 * DM + col;
                float* p1 = out + (size_t)r1 * DM + col;
                p0[0] = v00; p0[1] = v01;
                p1[0] = v10; p1[1] = v11;
            }
        }
    }
}

// ---------------------------------------------------------------------------
// TF32 flash attention. Block = 128 q x (head, batch), 128 threads = 4 warps,
// each warp 32 q rows x 64-key tile. P handled register-to-register via
// quad shuffles (no smem round trip). 2 CTAs/SM.
// ---------------------------------------------------------------------------
__global__ __launch_bounds__(128, 2) void attn_tf32(const float* __restrict__ mask,
                                                    float* __restrict__ outp)
{
    extern __shared__ __align__(16) unsigned smu[];
    unsigned* Qf = smu;              // [ktd8][mt8][lane*4+rg] = 8192 u32
    unsigned* Kf = Qf + 8192;        // [ktd8][ntk8][lane*2+rg] = 4096
    unsigned* Vf = Kf + 4096;        // [ktk8][ntd8][lane*2+rg] = 4096

    const int tid  = threadIdx.x;
    const int lane = tid & 31, wid = tid >> 5;
    const int g = lane >> 2, t = lane & 3;
    const int q0 = blockIdx.x * 128;
    const int h  = blockIdx.y;
    const int b  = blockIdx.z;
    const float* Qg = g_qh + (size_t)(b * NH + h) * SS * DH;
    const float* Kg = g_kh + (size_t)(b * NH + h) * SS * DH;
    const float* Vg = g_vh + (size_t)(b * NH + h) * SS * DH;
    const int mt0 = wid * 2;   // warp owns m16 tiles mt0, mt0+1 (32 q rows)

    float o[2][8][4];
    #pragma unroll
    for (int im = 0; im < 2; im++)
        #pragma unroll
        for (int j = 0; j < 8; j++)
            #pragma unroll
            for (int r = 0; r < 4; r++) o[im][j][r] = 0.f;
    float mrow[2][2] = {{-1e30f, -1e30f}, {-1e30f, -1e30f}};
    float lrow[2][2] = {{0.f, 0.f}, {0.f, 0.f}};

    // Stage Q tile (128x64) once: row pairs (q, q+8)
    #pragma unroll
    for (int i = 0; i < 8; i++) {
        int idx = i * 128 + tid;
        int dq = (idx & 15) << 2;     // 0..60
        int row_id = idx >> 4;        // 0..63
        int mt = row_id >> 3, rl = row_id & 7;
        const float* p = Qg + (size_t)(q0 + mt * 16 + rl) * DH + dq;
        float4 v0 = *(const float4*)p;
        float4 v1 = *(const float4*)(p + 8 * DH);
        float f0[4] = {v0.x, v0.y, v0.z, v0.w};
        float f1[4] = {v1.x, v1.y, v1.z, v1.w};
        int ktd = dq >> 3;
        int rb = ((dq >> 2) & 1) << 1;
        unsigned* base = &Qf[((ktd * 8 + mt) * 32 + (rl << 2)) * 4 + rb];
        #pragma unroll
        for (int j = 0; j < 4; j++) {
            uint2 pr = make_uint2(tf32r(f0[j]), tf32r(f1[j]));
            *(uint2*)(base + j * 4) = pr;
        }
    }
    __syncthreads();

    const int src0 = (lane & 28) | (t >> 1);
    const int src1 = src0 + 2;
    const bool hi = (t & 1) != 0;

    for (int k0 = 0; k0 < SS; k0 += 64) {
        // Stage K (64 keys x 64 d): d-pairs (d, d+4)
        #pragma unroll
        for (int i = 0; i < 4; i++) {
            int idx = i * 128 + tid;
            int dq = (idx & 7) << 3;      // 0,8,...,56
            int key = idx >> 3;           // 0..63
            const float* p = Kg + (size_t)(k0 + key) * DH + dq;
            float4 v0 = *(const float4*)p;
            float4 v1 = *(const float4*)(p + 4);
            float f0[4] = {v0.x, v0.y, v0.z, v0.w};
            float f1[4] = {v1.x, v1.y, v1.z, v1.w};
            int ktd = dq >> 3, ntk = key >> 3;
            unsigned* base = &Kf[((ktd * 8 + ntk) * 32 + ((key & 7) << 2)) * 2];
            #pragma unroll
            for (int j = 0; j < 4; j++) {
                uint2 pr = make_uint2(tf32r(f0[j]), tf32r(f1[j]));
                *(uint2*)(base + j * 2) = pr;
            }
        }
        // Stage V (64 keys x 64 d): key-pairs (key, key+4)
        #pragma unroll
        for (int i = 0; i < 4; i++) {
            int idx = i * 128 + tid;
            int dq = (idx & 15) << 2;     // 0..60
            int klid = idx >> 4;          // 0..31
            int ktk = klid >> 2, kr = klid & 3;
            const float* p = Vg + (size_t)(k0 + ktk * 8 + kr) * DH + dq;
            float4 v0 = *(const float4*)p;
            float4 v1 = *(const float4*)(p + 4 * DH);
            float f0[4] = {v0.x, v0.y, v0.z, v0.w};
            float f1[4] = {v1.x, v1.y, v1.z, v1.w};
            #pragma unroll
            for (int j = 0; j < 4; j++) {
                int d = dq + j, ntd = d >> 3;
                int ln = ((d & 7) << 2) | kr;
                uint2 pr = make_uint2(tf32r(f0[j]), tf32r(f1[j]));
                *(uint2*)&Vf[((ktk * 8 + ntd) * 32 + ln) * 2] = pr;
            }
        }
        __syncthreads();

        // Scores: 32q x 64k per warp
        float s[2][8][4];
        #pragma unroll
        for (int im = 0; im < 2; im++)
            #pragma unroll
            for (int j = 0; j < 8; j++)
                #pragma unroll
                for (int r = 0; r < 4; r++) s[im][j][r] = 0.f;

        #pragma unroll
        for (int ktd = 0; ktd < 8; ktd++) {
            unsigned a0[4], a1[4];
            *(uint4*)a0 = *(const uint4*)&Qf[((ktd * 8 + mt0) * 32 + lane) * 4];
            *(uint4*)a1 = *(const uint4*)&Qf[((ktd * 8 + mt0 + 1) * 32 + lane) * 4];
            #pragma unroll
            for (int nt = 0; nt < 8; nt++) {
                unsigned bk[2];
                *(uint2*)bk = *(const uint2*)&Kf[((ktd * 8 + nt) * 32 + lane) * 2];
                mma_tf32(s[0][nt], a0, bk);
                mma_tf32(s[1][nt], a1, bk);
            }
        }

        // Scale + mask
        #pragma unroll
        for (int im = 0; im < 2; im++) {
            int r0 = q0 + wid * 32 + im * 16 + g;
            int r1 = r0 + 8;
            #pragma unroll
            for (int nt = 0; nt < 8; nt++) {
                int col = k0 + nt * 8 + t * 2;
                float2 mk0 = __ldg((const float2*)(mask + (size_t)r0 * SS + col));
                float2 mk1 = __ldg((const float2*)(mask + (size_t)r1 * SS + col));
                s[im][nt][0] = s[im][nt][0] * 0.125f - 1e9f * mk0.x;
                s[im][nt][1] = s[im][nt][1] * 0.125f - 1e9f * mk0.y;
                s[im][nt][2] = s[im][nt][2] * 0.125f - 1e9f * mk1.x;
                s[im][nt][3] = s[im][nt][3] * 0.125f - 1e9f * mk1.y;
            }
        }

        // Online softmax per (im, row-half); stats shared within lane quad
        #pragma unroll
        for (int im = 0; im < 2; im++) {
            float mx0 = -1e30f, mx1 = -1e30f;
            #pragma unroll
            for (int nt = 0; nt < 8; nt++) {
                mx0 = fmaxf(mx0, fmaxf(s[im][nt][0], s[im][nt][1]));
                mx1 = fmaxf(mx1, fmaxf(s[im][nt][2], s[im][nt][3]));
            }
            mx0 = fmaxf(mx0, __shfl_xor_sync(0xffffffffu, mx0, 1));
            mx0 = fmaxf(mx0, __shfl_xor_sync(0xffffffffu, mx0, 2));
            mx1 = fmaxf(mx1, __shfl_xor_sync(0xffffffffu, mx1, 1));
            mx1 = fmaxf(mx1, __shfl_xor_sync(0xffffffffu, mx1, 2));

            float nm0 = fmaxf(mrow[im][0], mx0), nm1 = fmaxf(mrow[im][1], mx1);
            float al0 = __expf(mrow[im][0] - nm0), al1 = __expf(mrow[im][1] - nm1);
            float sum0 = 0.f, sum1 = 0.f;
            #pragma unroll
            for (int nt = 0; nt < 8; nt++) {
                float p0 = __expf(s[im][nt][0] - nm0);
                float p1 = __expf(s[im][nt][1] - nm0);
                float p2 = __expf(s[im][nt][2] - nm1);
                float p3 = __expf(s[im][nt][3] - nm1);
                s[im][nt][0] = p0; s[im][nt][1] = p1;
                s[im][nt][2] = p2; s[im][nt][3] = p3;
                sum0 += p0 + p1;
                sum1 += p2 + p3;
            }
            sum0 += __shfl_xor_sync(0xffffffffu, sum0, 1);
            sum0 += __shfl_xor_sync(0xffffffffu, sum0, 2);
            sum1 += __shfl_xor_sync(0xffffffffu, sum1, 1);
            sum1 += __shfl_xor_sync(0xffffffffu, sum1, 2);
            lrow[im][0] = lrow[im][0] * al0 + sum0;
            lrow[im][1] = lrow[im][1] * al1 + sum1;
            mrow[im][0] = nm0; mrow[im][1] = nm1;

            #pragma unroll
            for (int nt = 0; nt < 8; nt++) {
                o[im][nt][0] *= al0; o[im][nt][1] *= al0;
                o[im][nt][2] *= al1; o[im][nt][3] *= al1;
            }
        }

        // PV: C-frag -> A-frag conversion via quad shuffles, then mma
        #pragma unroll
        for (int kb = 0; kb < 8; kb++) {
            unsigned pa[2][4];
            #pragma unroll
            for (int im = 0; im < 2; im++) {
                float v0 = __shfl_sync(0xffffffffu, s[im][kb][0], src0);
                float v1 = __shfl_sync(0xffffffffu, s[im][kb][1], src0);
                float u0 = __shfl_sync(0xffffffffu, s[im][kb][2], src0);
                float u1 = __shfl_sync(0xffffffffu, s[im][kb][3], src0);
                float w0 = __shfl_sync(0xffffffffu, s[im][kb][0], src1);
                float w1 = __shfl_sync(0xffffffffu, s[im][kb][1], src1);
                float x0 = __shfl_sync(0xffffffffu, s[im][kb][2], src1);
                float x1 = __shfl_sync(0xffffffffu, s[im][kb][3], src1);
                pa[im][0] = tf32r(hi ? v1 : v0);
                pa[im][1] = tf32r(hi ? u1 : u0);
                pa[im][2] = tf32r(hi ? w1 : w0);
                pa[im][3] = tf32r(hi ? x1 : x0);
            }
            #pragma unroll
            for (int ntd = 0; ntd < 8; ntd++) {
                unsigned bv[2];
                *(uint2*)bv = *(const uint2*)&Vf[((kb * 8 + ntd) * 32 + lane) * 2];
                mma_tf32(o[0][ntd], pa[0], bv);
                mma_tf32(o[1][ntd], pa[1], bv);
            }
        }
        __syncthreads();
    }

    // Epilogue: normalize + write merged-head layout
    #pragma unroll
    for (int im = 0; im < 2; im++) {
        float inv0 = 1.0f / lrow[im][0], inv1 = 1.0f / lrow[im][1];
        int r0 = q0 + wid * 32 + im * 16 + g;
        int r1 = r0 + 8;
        #pragma unroll
        for (int ntd = 0; ntd < 8; ntd++) {
            int col = h * DH + ntd * 8 + t * 2;
            float2 v0 = make_float2(o[im][ntd][0] * inv0, o[im][ntd][1] * inv0);
            float2 v1 = make_float2(o[im][ntd][2] * inv1, o[im][ntd][3] * inv1);
            *(float2*)(outp + ((size_t)b * SS + r0) * DM + col) = v0;
            *(float2*)(outp + ((size_t)b * SS + r1) * DM + col) = v1;
        }
    }
}

// ---------------------------------------------------------------------------
extern "C" void kernel_launch(void* const* d_in, const int* in_sizes, int n_in,
                              void* d_out, int out_size)
{
    const float* q    = (const float*)d_in[0];
    const float* k    = (const float*)d_in[1];
    const float* v    = (const float*)d_in[2];
    const float* mask = (const float*)d_in[3];
    const float* wq   = (const float*)d_in[4];
    const float* bq   = (const float*)d_in[5];
    const float* wk   = (const float*)d_in[6];
    const float* bk   = (const float*)d_in[7];
    const float* wv   = (const float*)d_in[8];
    const float* bv   = (const float*)d_in[9];
    const float* wo   = (const float*)d_in[10];
    const float* bo   = (const float*)d_in[11];

    float *qh, *kh, *vh, *at;
    cudaGetSymbolAddress((void**)&qh, g_qh);
    cudaGetSymbolAddress((void**)&kh, g_kh);
    cudaGetSymbolAddress((void**)&vh, g_vh);
    cudaGetSymbolAddress((void**)&at, g_at);

    const int attn_smem = (8192 + 4096 + 4096) * (int)sizeof(unsigned);  // 64 KB
    cudaFuncSetAttribute(attn_tf32, cudaFuncAttributeMaxDynamicSharedMemorySize,
                         attn_smem);

    dim3 gg(DM / 128, MT / 128);
    gemm_tf32<<<gg, 128>>>(q, wq, bq, qh, 1);
    gemm_tf32<<<gg, 128>>>(k, wk, bk, kh, 1);
    gemm_tf32<<<gg, 128>>>(v, wv, bv, vh, 1);

    dim3 ga(SS / 128, NH, BB);
    attn_tf32<<<ga, 128, attn_smem>>>(mask, at);

    gemm_tf32<<<gg, 128>>>(at, wo, bo, (float*)d_out, 0);
}

// round 8
// speedup vs baseline: 1.5071x; 1.5071x over previous
#include <cuda_runtime.h>
#include <cstdint>

#define DM 1024
#define NH 16
#define DH 64
#define BB 2
#define SS 2048
#define MT (BB*SS)

// Scratch (device globals; no allocation allowed anywhere)
__device__ float g_qh[MT*DM];   // [B,H,S,DH]
__device__ float g_kh[MT*DM];
__device__ float g_vh[MT*DM];
__device__ float g_at[MT*DM];   // merged-head attention output [B,S,DM]

// ---------------------------------------------------------------------------
__device__ __forceinline__ unsigned tf32r(float x) {
    unsigned u;
    asm("cvt.rna.tf32.f32 %0, %1;" : "=r"(u) : "f"(x));
    return u;
}
__device__ __forceinline__ void mma_tf32(float c[4], const unsigned a[4],
                                         const unsigned b[2]) {
    asm volatile(
        "mma.sync.aligned.m16n8k8.row.col.f32.tf32.tf32.f32 "
        "{%0,%1,%2,%3}, {%4,%5,%6,%7}, {%8,%9}, {%0,%1,%2,%3};"
        : "+f"(c[0]), "+f"(c[1]), "+f"(c[2]), "+f"(c[3])
        : "r"(a[0]), "r"(a[1]), "r"(a[2]), "r"(a[3]), "r"(b[0]), "r"(b[1]));
}

struct GA { const float* A; const float* W; const float* bias; float* out; };
struct G3 { GA g[3]; };

// ---------------------------------------------------------------------------
// TF32 GEMM, double-buffered pipeline. out[M,1024] = A @ W + bias.
// Block 128x128, BK=16, 256 threads (8 warps, warp tile 32x64), 2 CTAs/SM.
// blockIdx.z selects one of up to 3 independent (A,W,bias,out) problems.
// ---------------------------------------------------------------------------
__global__ __launch_bounds__(256, 2) void gemm_tf32(G3 P, int split)
{
    __shared__ __align__(16) unsigned As[2][2048];   // [buf][kt2][mt8][lane*4+rg]
    __shared__ __align__(16) unsigned Bs[2][2048];   // [buf][kt2][nt16][lane*2+rg]

    const GA ga = P.g[blockIdx.z];
    const int tid = threadIdx.x, lane = tid & 31, wid = tid >> 5;
    const int g = lane >> 2, t = lane & 3;
    const int bm = blockIdx.y * 128, bn = blockIdx.x * 128;

    // A staging decode: thread -> row pair (m, m+8), k-quad
    const int a_mt = tid >> 5, a_rl = (tid >> 2) & 7;
    const int a_kq = (tid & 3) << 2;
    const int a_kt = a_kq >> 3;
    const int a_rgb = ((a_kq >> 2) & 1) << 1;
    const unsigned a_base = ((a_kt * 8 + a_mt) * 32 + a_rl * 4) * 4 + a_rgb;
    const float* Aptr = ga.A + (size_t)(bm + a_mt * 16 + a_rl) * DM + a_kq;

    // B staging decode: thread -> k-row pair (kk, kk+4), n-quad
    const int b_kid = tid >> 5, b_kt = b_kid >> 2, b_kr = b_kid & 3;
    const int b_n4 = (tid & 31) << 2;
    const int b_nt = b_n4 >> 3;
    const unsigned b_base = ((b_kt * 16 + b_nt) * 32 + ((b_n4 & 7) * 4 + b_kr)) * 2;
    const float* Wptr = ga.W + (size_t)(b_kt * 8 + b_kr) * DM + bn + b_n4;

    const int w_mt = (wid >> 1) * 2, w_nt = (wid & 1) * 8;

    float acc[2][8][4];
    #pragma unroll
    for (int im = 0; im < 2; im++)
        #pragma unroll
        for (int jn = 0; jn < 8; jn++)
            #pragma unroll
            for (int r = 0; r < 4; r++) acc[im][jn][r] = 0.f;

    float4 ra0, ra1, rb0, rb1;

#define G_LOAD(K0) do {                                                     \
    ra0 = *(const float4*)(Aptr + (K0));                                    \
    ra1 = *(const float4*)(Aptr + (K0) + 8 * DM);                           \
    rb0 = *(const float4*)(Wptr + (size_t)(K0) * DM);                       \
    rb1 = *(const float4*)(Wptr + (size_t)(K0) * DM + 4 * DM);              \
} while (0)

#define G_STORE(BUF) do {                                                   \
    float fa0[4] = {ra0.x, ra0.y, ra0.z, ra0.w};                            \
    float fa1[4] = {ra1.x, ra1.y, ra1.z, ra1.w};                            \
    float fb0[4] = {rb0.x, rb0.y, rb0.z, rb0.w};                            \
    float fb1[4] = {rb1.x, rb1.y, rb1.z, rb1.w};                            \
    _Pragma("unroll")                                                       \
    for (int j = 0; j < 4; j++) {                                           \
        uint2 pa = make_uint2(tf32r(fa0[j]), tf32r(fa1[j]));                \
        *(uint2*)&As[BUF][a_base + j * 4] = pa;                             \
        uint2 pb = make_uint2(tf32r(fb0[j]), tf32r(fb1[j]));                \
        *(uint2*)&Bs[BUF][b_base + j * 8] = pb;                             \
    }                                                                       \
} while (0)

    G_LOAD(0);
    G_STORE(0);
    __syncthreads();

    for (int kc = 0; kc < 64; kc++) {
        if (kc < 63) G_LOAD((kc + 1) * 16);
        const int buf = kc & 1;
        #pragma unroll
        for (int kt = 0; kt < 2; kt++) {
            unsigned a[2][4], b[8][2];
            #pragma unroll
            for (int im = 0; im < 2; im++)
                *(uint4*)a[im] =
                    *(const uint4*)&As[buf][((kt * 8 + w_mt + im) * 32 + lane) * 4];
            #pragma unroll
            for (int jn = 0; jn < 8; jn++)
                *(uint2*)b[jn] =
                    *(const uint2*)&Bs[buf][((kt * 16 + w_nt + jn) * 32 + lane) * 2];
            #pragma unroll
            for (int im = 0; im < 2; im++)
                #pragma unroll
                for (int jn = 0; jn < 8; jn++)
                    mma_tf32(acc[im][jn], a[im], b[jn]);
        }
        if (kc < 63) G_STORE((kc + 1) & 1);
        __syncthreads();
    }

    // Epilogue
    #pragma unroll
    for (int im = 0; im < 2; im++) {
        int r0 = bm + (wid >> 1) * 32 + im * 16 + g;
        int r1 = r0 + 8;
        #pragma unroll
        for (int jn = 0; jn < 8; jn++) {
            int col = bn + (wid & 1) * 64 + jn * 8 + t * 2;
            float b0 = ga.bias[col], b1 = ga.bias[col + 1];
            float v00 = acc[im][jn][0] + b0, v01 = acc[im][jn][1] + b1;
            float v10 = acc[im][jn][2] + b0, v11 = acc[im][jn][3] + b1;
            if (split) {
                int h = col >> 6, d = col & 63;
                int b_0 = r0 >> 11, s_0 = r0 & (SS - 1);
                int b_1 = r1 >> 11, s_1 = r1 & (SS - 1);
                float* p0 = ga.out + (((size_t)(b_0 * NH + h)) * SS + s_0) * DH + d;
                float* p1 = ga.out + (((size_t)(b_1 * NH + h)) * SS + s_1) * DH + d;
                p0[0] = v00; p0[1] = v01;
                p1[0] = v10; p1[1] = v11;
            } else {
                float* p0 = ga.out + (size_t)r0 * DM + col;
                float* p1 = ga.out + (size_t)r1 * DM + col;
                p0[0] = v00; p0[1] = v01;
                p1[0] = v10; p1[1] = v11;
            }
        }
    }
#undef G_LOAD
#undef G_STORE
}

// ---------------------------------------------------------------------------
// TF32 flash attention. Block = 128 q x (head, batch), 128 threads = 4 warps,
// each warp owns 32 q rows x 64-key tile. P is scattered into A-fragment
// layout in a per-warp smem region (STS.64 pairs, LDS.128 reads, only
// __syncwarp between).
// ---------------------------------------------------------------------------
__global__ __launch_bounds__(128) void attn_tf32(const float* __restrict__ mask,
                                                 float* __restrict__ outp)
{
    extern __shared__ __align__(16) unsigned smu[];
    unsigned* Qf = smu;              // [ktd8][mt8][lane*4+rg]   = 8192 u32
    unsigned* Kf = Qf + 8192;        // [ktd8][ntk8][lane*2+rg]  = 4096
    unsigned* Vf = Kf + 4096;        // [ktk8][ntd8][lane*2+rg]  = 4096
    unsigned* Pf = Vf + 4096;        // [wid4][ktk8][im2][lane*4+rg] = 8192

    const int tid  = threadIdx.x;
    const int lane = tid & 31, wid = tid >> 5;
    const int g = lane >> 2, t = lane & 3;
    const int q0 = blockIdx.x * 128;
    const int h  = blockIdx.y;
    const int b  = blockIdx.z;
    const float* Qg = g_qh + (size_t)(b * NH + h) * SS * DH;
    const float* Kg = g_kh + (size_t)(b * NH + h) * SS * DH;
    const float* Vg = g_vh + (size_t)(b * NH + h) * SS * DH;
    const int mt0 = wid * 2;

    float o[2][8][4];
    #pragma unroll
    for (int im = 0; im < 2; im++)
        #pragma unroll
        for (int j = 0; j < 8; j++)
            #pragma unroll
            for (int r = 0; r < 4; r++) o[im][j][r] = 0.f;
    float mrow[2][2] = {{-1e30f, -1e30f}, {-1e30f, -1e30f}};
    float lrow[2][2] = {{0.f, 0.f}, {0.f, 0.f}};

    // Stage Q tile (128x64) once: row pairs (q, q+8)
    #pragma unroll
    for (int i = 0; i < 8; i++) {
        int idx = i * 128 + tid;
        int dq = (idx & 15) << 2;
        int row_id = idx >> 4;
        int mt = row_id >> 3, rl = row_id & 7;
        const float* p = Qg + (size_t)(q0 + mt * 16 + rl) * DH + dq;
        float4 v0 = *(const float4*)p;
        float4 v1 = *(const float4*)(p + 8 * DH);
        float f0[4] = {v0.x, v0.y, v0.z, v0.w};
        float f1[4] = {v1.x, v1.y, v1.z, v1.w};
        int ktd = dq >> 3;
        int rb = ((dq >> 2) & 1) << 1;
        unsigned* base = &Qf[((ktd * 8 + mt) * 32 + (rl << 2)) * 4 + rb];
        #pragma unroll
        for (int j = 0; j < 4; j++) {
            uint2 pr = make_uint2(tf32r(f0[j]), tf32r(f1[j]));
            *(uint2*)(base + j * 4) = pr;
        }
    }
    __syncthreads();

    for (int k0 = 0; k0 < SS; k0 += 64) {
        // Stage K (64 keys x 64 d): d-pairs (d, d+4)
        #pragma unroll
        for (int i = 0; i < 4; i++) {
            int idx = i * 128 + tid;
            int dq = (idx & 7) << 3;
            int key = idx >> 3;
            const float* p = Kg + (size_t)(k0 + key) * DH + dq;
            float4 v0 = *(const float4*)p;
            float4 v1 = *(const float4*)(p + 4);
            float f0[4] = {v0.x, v0.y, v0.z, v0.w};
            float f1[4] = {v1.x, v1.y, v1.z, v1.w};
            int ktd = dq >> 3, ntk = key >> 3;
            unsigned* base = &Kf[((ktd * 8 + ntk) * 32 + ((key & 7) << 2)) * 2];
            #pragma unroll
            for (int j = 0; j < 4; j++) {
                uint2 pr = make_uint2(tf32r(f0[j]), tf32r(f1[j]));
                *(uint2*)(base + j * 2) = pr;
            }
        }
        // Stage V (64 keys x 64 d): key-pairs (key, key+4)
        #pragma unroll
        for (int i = 0; i < 4; i++) {
            int idx = i * 128 + tid;
            int dq = (idx & 15) << 2;
            int klid = idx >> 4;
            int ktk = klid >> 2, kr = klid & 3;
            const float* p = Vg + (size_t)(k0 + ktk * 8 + kr) * DH + dq;
            float4 v0 = *(const float4*)p;
            float4 v1 = *(const float4*)(p + 4 * DH);
            float f0[4] = {v0.x, v0.y, v0.z, v0.w};
            float f1[4] = {v1.x, v1.y, v1.z, v1.w};
            #pragma unroll
            for (int j = 0; j < 4; j++) {
                int d = dq + j, ntd = d >> 3;
                int ln = ((d & 7) << 2) | kr;
                uint2 pr = make_uint2(tf32r(f0[j]), tf32r(f1[j]));
                *(uint2*)&Vf[((ktk * 8 + ntd) * 32 + ln) * 2] = pr;
            }
        }
        __syncthreads();

        // Scores: 32q x 64k per warp
        float s[2][8][4];
        #pragma unroll
        for (int im = 0; im < 2; im++)
            #pragma unroll
            for (int j = 0; j < 8; j++)
                #pragma unroll
                for (int r = 0; r < 4; r++) s[im][j][r] = 0.f;

        #pragma unroll
        for (int ktd = 0; ktd < 8; ktd++) {
            unsigned a0[4], a1[4];
            *(uint4*)a0 = *(const uint4*)&Qf[((ktd * 8 + mt0) * 32 + lane) * 4];
            *(uint4*)a1 = *(const uint4*)&Qf[((ktd * 8 + mt0 + 1) * 32 + lane) * 4];
            #pragma unroll
            for (int nt = 0; nt < 8; nt++) {
                unsigned bk[2];
                *(uint2*)bk = *(const uint2*)&Kf[((ktd * 8 + nt) * 32 + lane) * 2];
                mma_tf32(s[0][nt], a0, bk);
                mma_tf32(s[1][nt], a1, bk);
            }
        }

        // Scale + mask
        #pragma unroll
        for (int im = 0; im < 2; im++) {
            int r0 = q0 + wid * 32 + im * 16 + g;
            int r1 = r0 + 8;
            #pragma unroll
            for (int nt = 0; nt < 8; nt++) {
                int col = k0 + nt * 8 + t * 2;
                float2 mk0 = __ldg((const float2*)(mask + (size_t)r0 * SS + col));
                float2 mk1 = __ldg((const float2*)(mask + (size_t)r1 * SS + col));
                s[im][nt][0] = s[im][nt][0] * 0.125f - 1e9f * mk0.x;
                s[im][nt][1] = s[im][nt][1] * 0.125f - 1e9f * mk0.y;
                s[im][nt][2] = s[im][nt][2] * 0.125f - 1e9f * mk1.x;
                s[im][nt][3] = s[im][nt][3] * 0.125f - 1e9f * mk1.y;
            }
        }

        // Online softmax per (im, row-half); stats shared within lane quad
        #pragma unroll
        for (int im = 0; im < 2; im++) {
            float mx0 = -1e30f, mx1 = -1e30f;
            #pragma unroll
            for (int nt = 0; nt < 8; nt++) {
                mx0 = fmaxf(mx0, fmaxf(s[im][nt][0], s[im][nt][1]));
                mx1 = fmaxf(mx1, fmaxf(s[im][nt][2], s[im][nt][3]));
            }
            mx0 = fmaxf(mx0, __shfl_xor_sync(0xffffffffu, mx0, 1));
            mx0 = fmaxf(mx0, __shfl_xor_sync(0xffffffffu, mx0, 2));
            mx1 = fmaxf(mx1, __shfl_xor_sync(0xffffffffu, mx1, 1));
            mx1 = fmaxf(mx1, __shfl_xor_sync(0xffffffffu, mx1, 2));

            float nm0 = fmaxf(mrow[im][0], mx0), nm1 = fmaxf(mrow[im][1], mx1);
            float al0 = __expf(mrow[im][0] - nm0), al1 = __expf(mrow[im][1] - nm1);
            float sum0 = 0.f, sum1 = 0.f;
            #pragma unroll
            for (int nt = 0; nt < 8; nt++) {
                float p0 = __expf(s[im][nt][0] - nm0);
                float p1 = __expf(s[im][nt][1] - nm0);
                float p2 = __expf(s[im][nt][2] - nm1);
                float p3 = __expf(s[im][nt][3] - nm1);
                s[im][nt][0] = p0; s[im][nt][1] = p1;
                s[im][nt][2] = p2; s[im][nt][3] = p3;
                sum0 += p0 + p1;
                sum1 += p2 + p3;
            }
            sum0 += __shfl_xor_sync(0xffffffffu, sum0, 1);
            sum0 += __shfl_xor_sync(0xffffffffu, sum0, 2);
            sum1 += __shfl_xor_sync(0xffffffffu, sum1, 1);
            sum1 += __shfl_xor_sync(0xffffffffu, sum1, 2);
            lrow[im][0] = lrow[im][0] * al0 + sum0;
            lrow[im][1] = lrow[im][1] * al1 + sum1;
            mrow[im][0] = nm0; mrow[im][1] = nm1;

            #pragma unroll
            for (int nt = 0; nt < 8; nt++) {
                o[im][nt][0] *= al0; o[im][nt][1] *= al0;
                o[im][nt][2] *= al1; o[im][nt][3] *= al1;
            }
        }

        // Scatter P (C-frag) into A-frag layout: per nt, two STS.64
        // (c0,c2) -> (ln0, rg {rgb, rgb+1}), (c1,c3) -> (ln0+1, same rgs)
        {
            const int ln0 = g * 4 + ((2 * t) & 3);
            const int rgb = (t >> 1) << 1;
            #pragma unroll
            for (int im = 0; im < 2; im++) {
                #pragma unroll
                for (int nt = 0; nt < 8; nt++) {
                    unsigned* base = &Pf[((wid * 8 + nt) * 2 + im) * 128];
                    uint2 p02 = make_uint2(tf32r(s[im][nt][0]), tf32r(s[im][nt][2]));
                    *(uint2*)&base[ln0 * 4 + rgb] = p02;
                    uint2 p13 = make_uint2(tf32r(s[im][nt][1]), tf32r(s[im][nt][3]));
                    *(uint2*)&base[(ln0 + 1) * 4 + rgb] = p13;
                }
            }
        }
        __syncwarp();

        // PV: A-frag LDS.128 per (ktk, im), B from Vf
        #pragma unroll
        for (int ktk = 0; ktk < 8; ktk++) {
            unsigned ap[2][4];
            *(uint4*)ap[0] = *(const uint4*)&Pf[(((wid * 8 + ktk) * 2 + 0) * 128) + lane * 4];
            *(uint4*)ap[1] = *(const uint4*)&Pf[(((wid * 8 + ktk) * 2 + 1) * 128) + lane * 4];
            #pragma unroll
            for (int ntd = 0; ntd < 8; ntd++) {
                unsigned bv[2];
                *(uint2*)bv = *(const uint2*)&Vf[((ktk * 8 + ntd) * 32 + lane) * 2];
                mma_tf32(o[0][ntd], ap[0], bv);
                mma_tf32(o[1][ntd], ap[1], bv);
            }
        }
        __syncthreads();
    }

    // Epilogue: normalize + write merged-head layout
    #pragma unroll
    for (int im = 0; im < 2; im++) {
        float inv0 = 1.0f / lrow[im][0], inv1 = 1.0f / lrow[im][1];
        int r0 = q0 + wid * 32 + im * 16 + g;
        int r1 = r0 + 8;
        #pragma unroll
        for (int ntd = 0; ntd < 8; ntd++) {
            int col = h * DH + ntd * 8 + t * 2;
            float2 v0 = make_float2(o[im][ntd][0] * inv0, o[im][ntd][1] * inv0);
            float2 v1 = make_float2(o[im][ntd][2] * inv1, o[im][ntd][3] * inv1);
            *(float2*)(outp + ((size_t)b * SS + r0) * DM + col) = v0;
            *(float2*)(outp + ((size_t)b * SS + r1) * DM + col) = v1;
        }
    }
}

// ---------------------------------------------------------------------------
extern "C" void kernel_launch(void* const* d_in, const int* in_sizes, int n_in,
                              void* d_out, int out_size)
{
    const float* q    = (const float*)d_in[0];
    const float* k    = (const float*)d_in[1];
    const float* v    = (const float*)d_in[2];
    const float* mask = (const float*)d_in[3];
    const float* wq   = (const float*)d_in[4];
    const float* bq   = (const float*)d_in[5];
    const float* wk   = (const float*)d_in[6];
    const float* bk   = (const float*)d_in[7];
    const float* wv   = (const float*)d_in[8];
    const float* bv   = (const float*)d_in[9];
    const float* wo   = (const float*)d_in[10];
    const float* bo   = (const float*)d_in[11];

    float *qh, *kh, *vh, *at;
    cudaGetSymbolAddress((void**)&qh, g_qh);
    cudaGetSymbolAddress((void**)&kh, g_kh);
    cudaGetSymbolAddress((void**)&vh, g_vh);
    cudaGetSymbolAddress((void**)&at, g_at);

    const int attn_smem = (8192 + 4096 + 4096 + 8192) * (int)sizeof(unsigned); // 96 KB
    cudaFuncSetAttribute(attn_tf32, cudaFuncAttributeMaxDynamicSharedMemorySize,
                         attn_smem);

    // Fused Q/K/V projections (independent problems, z-indexed)
    G3 pqkv;
    pqkv.g[0] = GA{q, wq, bq, qh};
    pqkv.g[1] = GA{k, wk, bk, kh};
    pqkv.g[2] = GA{v, wv, bv, vh};
    dim3 gqkv(DM / 128, MT / 128, 3);
    gemm_tf32<<<gqkv, 256>>>(pqkv, 1);

    dim3 ga(SS / 128, NH, BB);
    attn_tf32<<<ga, 128, attn_smem>>>(mask, at);

    G3 po;
    po.g[0] = GA{at, wo, bo, (float*)d_out};
    po.g[1] = po.g[0];
    po.g[2] = po.g[0];
    dim3 go(DM / 128, MT / 128, 1);
    gemm_tf32<<<go, 256>>>(po, 0);
}